// round 15
// baseline (speedup 1.0000x reference)
#include <cuda_runtime.h>
#include <cuda_fp16.h>
#include <math.h>
#include <stdint.h>

// Problem constants
#define NTOK 8192
#define DIM  1024
#define NE   16
#define CAPE 1024
#define NS   (NTOK*2)

// ---------------- scratch (static device globals) ----------------------------
__device__ float              g_gate[NS];
__device__ unsigned long long g_key[NS];
__device__ int                g_eid[NS];
__device__ int                g_cnt[NE];
__device__ int                g_list[NE*NS];
__device__ unsigned long long g_lkey[NE*NS];
__device__ int                g_keptcnt[NE];
__device__ int                g_kept[NE*CAPE];
__device__ unsigned char      g_keep[NS];
__device__ __half             g_Yh[(size_t)NS*DIM];          // 32MB fp16 expert outputs
__device__ __half             g_Ax[(size_t)NTOK*DIM];        // 16MB fp16(x) all tokens
__device__ __half             g_Bw[(size_t)NE*DIM*DIM];      // 32MB flat fp16(w)

// ---------------- helpers (baseline PTX only: sm_80-level features) ----------
__device__ __forceinline__ uint32_t smem_u32(const void* p) {
    uint32_t a;
    asm("{ .reg .u64 t; cvta.to.shared.u64 t, %1; cvt.u32.u64 %0, t; }" : "=r"(a) : "l"(p));
    return a;
}
__device__ __forceinline__ void cp16(uint32_t d, const void* s) {
    asm volatile("cp.async.cg.shared.global [%0], [%1], 16;" :: "r"(d), "l"(s));
}
__device__ __forceinline__ void cp_commit() {
    asm volatile("cp.async.commit_group;" ::: "memory");
}
__device__ __forceinline__ void ldmx4(uint32_t* r, uint32_t addr) {
    asm volatile("ldmatrix.sync.aligned.m8n8.x4.shared.b16 {%0,%1,%2,%3}, [%4];"
                 : "=r"(r[0]), "=r"(r[1]), "=r"(r[2]), "=r"(r[3]) : "r"(addr));
}
__device__ __forceinline__ void mma_f16(float* c, const uint32_t* a, uint32_t b0, uint32_t b1) {
    asm volatile("mma.sync.aligned.m16n8k16.row.col.f32.f16.f16.f32 "
                 "{%0,%1,%2,%3}, {%4,%5,%6,%7}, {%8,%9}, {%0,%1,%2,%3};"
                 : "+f"(c[0]), "+f"(c[1]), "+f"(c[2]), "+f"(c[3])
                 : "r"(a[0]), "r"(a[1]), "r"(a[2]), "r"(a[3]), "r"(b0), "r"(b1));
}

// ---------------- kernel 1: gating + fp16 convert + counter reset ------------
__global__ void gate_kernel(const float* __restrict__ x,
                            const float* __restrict__ gw,
                            const float* __restrict__ gb) {
    // fold init: block 0 resets counters (all gate blocks finish before build)
    if (blockIdx.x == 0 && threadIdx.x < NE) {
        g_cnt[threadIdx.x] = 0;
        g_keptcnt[threadIdx.x] = 0;
    }

    int warp = (blockIdx.x * blockDim.x + threadIdx.x) >> 5;
    int lane = threadIdx.x & 31;
    if (warp >= NTOK) return;
    const float* xr = x + (size_t)warp * DIM;
    __half* oh = g_Ax + (size_t)warp * DIM;

    float acc[NE];
#pragma unroll
    for (int e = 0; e < NE; e++) acc[e] = 0.f;

#pragma unroll
    for (int i = 0; i < 4; i++) {
        int chunk = i * 32 + lane;              // 128 chunks of 8 elems
        float4 v0 = *(const float4*)(xr + chunk * 8);
        float4 v1 = *(const float4*)(xr + chunk * 8 + 4);
        float f[8] = { v0.x, v0.y, v0.z, v0.w, v1.x, v1.y, v1.z, v1.w };

        unsigned short h[8];
#pragma unroll
        for (int j = 0; j < 8; j++) h[j] = __half_as_ushort(__float2half_rn(f[j]));
        *(uint4*)(oh + chunk * 8) =
            make_uint4((uint32_t)h[0] | ((uint32_t)h[1] << 16),
                       (uint32_t)h[2] | ((uint32_t)h[3] << 16),
                       (uint32_t)h[4] | ((uint32_t)h[5] << 16),
                       (uint32_t)h[6] | ((uint32_t)h[7] << 16));

#pragma unroll
        for (int j = 0; j < 8; j++) {
            int d = chunk * 8 + j;
            const float4* g4 = (const float4*)(gw + d * NE);
#pragma unroll
            for (int q = 0; q < 4; q++) {
                float4 w = g4[q];
                acc[4*q+0] += f[j] * w.x;
                acc[4*q+1] += f[j] * w.y;
                acc[4*q+2] += f[j] * w.z;
                acc[4*q+3] += f[j] * w.w;
            }
        }
    }

#pragma unroll
    for (int e = 0; e < NE; e++) {
        float v = acc[e];
#pragma unroll
        for (int o = 16; o > 0; o >>= 1) v += __shfl_xor_sync(0xffffffffu, v, o);
        acc[e] = v;
    }

    if (lane == 0) {
        float v0 = -1e30f, v1 = -1e30f;
        int   i0 = 0, i1 = 0;
#pragma unroll
        for (int e = 0; e < NE; e++) {
            float v = acc[e] + gb[e];
            if (v > v0)      { v1 = v0; i1 = i0; v0 = v; i0 = e; }
            else if (v > v1) { v1 = v;  i1 = e; }
        }
        float t  = expf(v1 - v0);
        float s  = 1.f / (1.f + t);
        float g0 = s, g1 = t * s;        // g0 >= 0.5 always

        int s0 = 2 * warp, s1 = s0 + 1;
        g_gate[s0] = g0;  g_gate[s1] = g1;
        g_eid[s0]  = i0;  g_eid[s1]  = i1;
        unsigned long long sb = (unsigned long long)__float_as_uint(g0);
        g_key[s0] = (sb << 14) | (unsigned long long)(NS - 1 - s0);
        g_key[s1] = (sb << 14) | (unsigned long long)(NS - 1 - s1);
    }
}

// ---------------- kernel 2: slot lists, block-aggregated atomics -------------
__global__ void build_kernel() {
    __shared__ int lcnt[NE];
    __shared__ int lbase[NE];
    int t = threadIdx.x;
    int s = blockIdx.x * 256 + t;
    if (t < NE) lcnt[t] = 0;
    __syncthreads();
    int e = g_eid[s];
    int p = atomicAdd(&lcnt[e], 1);
    __syncthreads();
    if (t < NE) lbase[t] = atomicAdd(&g_cnt[t], lcnt[t]);
    __syncthreads();
    int pos = lbase[e] + p;
    g_list[e * NS + pos] = s;
    g_lkey[e * NS + pos] = g_key[s];
}

// ---------------- kernel 3: histogram-select capacity ranking ----------------
#define NBUCK 16384
#define BLCAP 8192
#define RSMEM (NBUCK*4 + BLCAP*8 + BLCAP*4)

__device__ __forceinline__ int key_bucket(unsigned long long k) {
    int diff = (int)(uint32_t)(k >> 14) - 0x3F000000;
    diff >>= 9;
    return diff < 0 ? 0 : (diff > NBUCK - 1 ? NBUCK - 1 : diff);
}

__global__ void rank_kernel() {
    extern __shared__ char rsm[];
    int* hist = (int*)rsm;
    unsigned long long* lkey = (unsigned long long*)(rsm + NBUCK * 4);
    int* lslot = (int*)(rsm + NBUCK * 4 + BLCAP * 8);

    __shared__ int ps[256];
    __shared__ int suf[256];
    __shared__ int sB, sAbove, sNB;

    int e = blockIdx.x;
    int c = g_cnt[e];
    int t = threadIdx.x;

    for (int i = t; i < NBUCK; i += 256) hist[i] = 0;
    if (t == 0) { sB = -1; sAbove = 0; sNB = 0; }
    __syncthreads();

    for (int i = t; i < c; i += 256)
        atomicAdd(&hist[key_bucket(g_lkey[e * NS + i])], 1);
    __syncthreads();

    int local = 0;
#pragma unroll 8
    for (int j = 0; j < 64; j++) local += hist[t * 64 + j];
    ps[t] = local;
    __syncthreads();
    if (t == 0) {
        int run = 0;
        for (int j = 255; j >= 0; j--) { suf[j] = run; run += ps[j]; }
    }
    __syncthreads();
    if (suf[t] < CAPE && CAPE <= suf[t] + ps[t]) {
        int running = suf[t];
        for (int j = 63; j >= 0; j--) {
            int b = t * 64 + j;
            int h = hist[b];
            if (running < CAPE && CAPE <= running + h) { sB = b; sAbove = running; }
            running += h;
        }
    }
    __syncthreads();
    int B = sB, above = sAbove;

    for (int i = t; i < c; i += 256) {
        unsigned long long k = g_lkey[e * NS + i];
        int slot = g_list[e * NS + i];
        int b = key_bucket(k);
        if (b > B || B < 0) {
            g_keep[slot] = 1;
            int p = atomicAdd(&g_keptcnt[e], 1);
            g_kept[e * CAPE + p] = slot;
        } else if (b < B) {
            g_keep[slot] = 0;
        } else {
            int p = atomicAdd(&sNB, 1);
            if (p < BLCAP) { lkey[p] = k; lslot[p] = slot; }
            else {
                int cnt = 0;
                for (int j = 0; j < c; j++) cnt += (g_lkey[e * NS + j] > k) ? 1 : 0;
                bool kp = cnt < CAPE;
                g_keep[slot] = kp ? 1 : 0;
                if (kp) { int q = atomicAdd(&g_keptcnt[e], 1); g_kept[e * CAPE + q] = slot; }
            }
        }
    }
    __syncthreads();

    int nb = sNB < BLCAP ? sNB : BLCAP;
    bool overflow = sNB > BLCAP;
    for (int i = t; i < nb; i += 256) {
        unsigned long long k = lkey[i];
        int slot = lslot[i];
        int cnt = above;
        if (!overflow) {
            for (int j = 0; j < nb; j++) cnt += (lkey[j] > k) ? 1 : 0;
        } else {
            cnt = 0;
            for (int j = 0; j < c; j++) cnt += (g_lkey[e * NS + j] > k) ? 1 : 0;
        }
        bool kp = cnt < CAPE;
        g_keep[slot] = kp ? 1 : 0;
        if (kp) { int p = atomicAdd(&g_keptcnt[e], 1); g_kept[e * CAPE + p] = slot; }
    }
}

// ---------------- kernel 4: convert expert weights to fp16 (8 floats/thread) -
__global__ void convert_w_kernel(const float* __restrict__ ew) {
    size_t i8 = (size_t)blockIdx.x * blockDim.x + threadIdx.x;
    size_t g  = i8 * 8;
    float4 v0 = *(const float4*)(ew + g);
    float4 v1 = *(const float4*)(ew + g + 4);
    unsigned short h[8] = {
        __half_as_ushort(__float2half_rn(v0.x)), __half_as_ushort(__float2half_rn(v0.y)),
        __half_as_ushort(__float2half_rn(v0.z)), __half_as_ushort(__float2half_rn(v0.w)),
        __half_as_ushort(__float2half_rn(v1.x)), __half_as_ushort(__float2half_rn(v1.y)),
        __half_as_ushort(__float2half_rn(v1.z)), __half_as_ushort(__float2half_rn(v1.w)) };
    *(uint4*)(g_Bw + g) =
        make_uint4((uint32_t)h[0] | ((uint32_t)h[1] << 16),
                   (uint32_t)h[2] | ((uint32_t)h[3] << 16),
                   (uint32_t)h[4] | ((uint32_t)h[5] << 16),
                   (uint32_t)h[6] | ((uint32_t)h[7] << 16));
}

// ---------------- kernel 5: warp-MMA (HMMA) expert GEMM, K=1024 --------------
// PROVEN CONFIG (round-8): BM=128, BN=128, BK=32, 4-stage cp.async,
// single sync per k-chunk, prefetch right after barrier.
#define GBM 128
#define GBN 128
#define NKC 32
#define NSTAGE 4
#define STAGE_BYTES 16384                       // A 8KB + B 8KB
#define GEMM_SMEM (NSTAGE*STAGE_BYTES + GBM*8)

struct GCtx {
    const __half* Bb;
    const int* stok;       // smem token table
    uint32_t sb;
    int t;
};

__device__ __forceinline__ void g_load(const GCtx& c, int kc) {
    int k0 = kc * 32;
    uint32_t st = c.sb + (kc % NSTAGE) * STAGE_BYTES;
#pragma unroll
    for (int j = 0; j < 2; j++) {               // A: 128 rows x 4 chunks(16B)
        int s = c.t + 256 * j;
        int row = s >> 2, ch = s & 3;
        uint32_t dst = st + row * 64 + ((ch ^ ((row >> 1) & 3)) << 4);
        cp16(dst, g_Ax + (size_t)c.stok[row] * DIM + k0 + ch * 8);
    }
#pragma unroll
    for (int j = 0; j < 2; j++) {               // B: 128 rows x 4 chunks(16B)
        int s = c.t + 256 * j;
        int row = s >> 2, ch = s & 3;
        uint32_t dst = st + 8192 + row * 64 + ((ch ^ ((row >> 1) & 3)) << 4);
        cp16(dst, c.Bb + (size_t)row * DIM + k0 + ch * 8);
    }
    cp_commit();
}

__global__ void __launch_bounds__(256, 2)
moe_gemm_mma(const float* __restrict__ eb) {
    extern __shared__ char smem[];
    int e    = blockIdx.z;
    int mcnt = g_keptcnt[e];
    int m0   = blockIdx.y * GBM;
    if (m0 >= mcnt) return;
    int n0   = blockIdx.x * GBN;

    uint32_t sb = smem_u32(smem);
    int t = threadIdx.x;
    int w = t >> 5, l = t & 31;
    int wm = w & 3, wn = w >> 2;

    int* sslot = (int*)(smem + NSTAGE * STAGE_BYTES);
    int* stok  = sslot + GBM;
    if (t < GBM) {
        int mi = m0 + t;
        int slot = (mi < mcnt) ? g_kept[e * CAPE + mi] : -1;
        sslot[t] = slot;
        stok[t]  = (slot >= 0) ? (slot >> 1) : 0;
    }
    __syncthreads();

    GCtx c;
    c.Bb   = g_Bw + (size_t)(e * DIM + n0) * DIM;
    c.stok = stok;
    c.sb   = sb;
    c.t    = t;

    g_load(c, 0);
    g_load(c, 1);
    g_load(c, 2);

    float acc[2][8][4];
#pragma unroll
    for (int i = 0; i < 2; i++)
#pragma unroll
        for (int j = 0; j < 8; j++)
#pragma unroll
            for (int q = 0; q < 4; q++) acc[i][j][q] = 0.f;

    int sub = l >> 3, lr = l & 7;
    int a_row = wm * 32 + lr + ((sub & 1) << 3);   // + mt*16
    int a_cs  = sub >> 1;
    int b_row = wn * 64 + lr + ((sub >> 1) << 3);  // + j*16
    int b_cs  = sub & 1;

    for (int kc = 0; kc < NKC; kc++) {
        asm volatile("cp.async.wait_group 2;" ::: "memory");
        __syncthreads();
        // prefetch stage kc+3 (writes stage (kc-1)%4; all warps finished its
        // compute before this iteration's barrier)
        if (kc + 3 < NKC) g_load(c, kc + 3);
        else cp_commit();

        uint32_t sA = sb + (kc % NSTAGE) * STAGE_BYTES;
        uint32_t sB = sA + 8192;
#pragma unroll
        for (int ks = 0; ks < 2; ks++) {
            uint32_t areg[2][4];
#pragma unroll
            for (int mt = 0; mt < 2; mt++) {
                int row = a_row + mt * 16;
                int kch = ks * 2 + a_cs;
                ldmx4(areg[mt], sA + row * 64 + ((kch ^ ((row >> 1) & 3)) << 4));
            }
#pragma unroll
            for (int j = 0; j < 4; j++) {
                int row = b_row + j * 16;
                int kch = ks * 2 + b_cs;
                uint32_t breg[4];
                ldmx4(breg, sB + row * 64 + ((kch ^ ((row >> 1) & 3)) << 4));
#pragma unroll
                for (int mt = 0; mt < 2; mt++) {
                    mma_f16(acc[mt][2*j],   areg[mt], breg[0], breg[1]);
                    mma_f16(acc[mt][2*j+1], areg[mt], breg[2], breg[3]);
                }
            }
        }
    }

    // epilogue: bias + scatter fp16 to per-slot Y
    const float* br = eb + (size_t)e * DIM + n0;
#pragma unroll
    for (int mt = 0; mt < 2; mt++) {
        int r0 = wm * 32 + mt * 16 + (l >> 2);
        int s0 = sslot[r0], s1 = sslot[r0 + 8];
#pragma unroll
        for (int nt = 0; nt < 8; nt++) {
            int col = wn * 64 + nt * 8 + (l & 3) * 2;
            float2 bv = *(const float2*)(br + col);
            if (s0 >= 0) {
                __half2 h = __floats2half2_rn(acc[mt][nt][0] + bv.x, acc[mt][nt][1] + bv.y);
                *(__half2*)(g_Yh + (size_t)s0 * DIM + n0 + col) = h;
            }
            if (s1 >= 0) {
                __half2 h = __floats2half2_rn(acc[mt][nt][2] + bv.x, acc[mt][nt][3] + bv.y);
                *(__half2*)(g_Yh + (size_t)s1 * DIM + n0 + col) = h;
            }
        }
    }
}

// ---------------- kernel 6: combine ------------------------------------------
__global__ void combine_kernel(const float* __restrict__ x, float* __restrict__ out) {
    int idx = blockIdx.x * blockDim.x + threadIdx.x;
    if (idx >= NTOK * DIM / 4) return;
    int n  = idx >> 8;
    int dq = idx & 255;

    float g0 = g_gate[2 * n], g1 = g_gate[2 * n + 1];
    bool  k0 = g_keep[2 * n] != 0, k1 = g_keep[2 * n + 1] != 0;

    float4 xv = ((const float4*)x)[(size_t)n * 256 + dq];

    float y0[4], y1[4];
    if (k0) {
        const __half2* p = (const __half2*)(g_Yh + (size_t)(2 * n) * DIM + dq * 4);
        float2 a = __half22float2(p[0]), b = __half22float2(p[1]);
        y0[0] = a.x; y0[1] = a.y; y0[2] = b.x; y0[3] = b.y;
    } else { y0[0] = xv.x; y0[1] = xv.y; y0[2] = xv.z; y0[3] = xv.w; }
    if (k1) {
        const __half2* p = (const __half2*)(g_Yh + (size_t)(2 * n + 1) * DIM + dq * 4);
        float2 a = __half22float2(p[0]), b = __half22float2(p[1]);
        y1[0] = a.x; y1[1] = a.y; y1[2] = b.x; y1[3] = b.y;
    } else { y1[0] = xv.x; y1[1] = xv.y; y1[2] = xv.z; y1[3] = xv.w; }

    float4 o;
    o.x = g0 * y0[0] + g1 * y1[0];
    o.y = g0 * y0[1] + g1 * y1[1];
    o.z = g0 * y0[2] + g1 * y1[2];
    o.w = g0 * y0[3] + g1 * y1[3];
    ((float4*)out)[idx] = o;
}

// ---------------- launch ------------------------------------------------------
extern "C" void kernel_launch(void* const* d_in, const int* in_sizes, int n_in,
                              void* d_out, int out_size) {
    const float* moe_inp  = (const float*)d_in[0];
    const float* gate_w   = (const float*)d_in[1];
    const float* gate_b   = (const float*)d_in[2];
    const float* expert_w = (const float*)d_in[3];
    const float* expert_b = (const float*)d_in[4];
    float* out = (float*)d_out;

    (void)in_sizes; (void)n_in; (void)out_size;

    cudaFuncSetAttribute(rank_kernel, cudaFuncAttributeMaxDynamicSharedMemorySize, RSMEM);
    cudaFuncSetAttribute(moe_gemm_mma, cudaFuncAttributeMaxDynamicSharedMemorySize,
                         GEMM_SMEM);

    gate_kernel<<<NTOK / 8, 256>>>(moe_inp, gate_w, gate_b);
    convert_w_kernel<<<(NE * DIM * DIM / 8) / 256, 256>>>(expert_w);
    build_kernel<<<NS / 256, 256>>>();
    rank_kernel<<<NE, 256, RSMEM>>>();
    moe_gemm_mma<<<dim3(DIM / GBN, CAPE / GBM, NE), 256, GEMM_SMEM>>>(expert_b);
    combine_kernel<<<(NTOK * DIM / 4 + 255) / 256, 256>>>(moe_inp, out);
}

// round 16
// speedup vs baseline: 1.2200x; 1.2200x over previous
#include <cuda_runtime.h>
#include <cuda_fp16.h>
#include <math.h>
#include <stdint.h>

// Problem constants
#define NTOK 8192
#define DIM  1024
#define NE   16
#define CAPE 1024
#define NS   (NTOK*2)

// ---------------- scratch (static device globals) ----------------------------
__device__ float              g_gate[NS];
__device__ unsigned long long g_key[NS];
__device__ int                g_eid[NS];
__device__ int                g_cnt[NE];
__device__ int                g_list[NE*NS];
__device__ unsigned long long g_lkey[NE*NS];
__device__ int                g_keptcnt[NE];
__device__ int                g_kept[NE*CAPE];
__device__ unsigned char      g_keep[NS];
__device__ __half             g_Yh[(size_t)NS*DIM];          // 32MB fp16 expert outputs
__device__ __half             g_Ax[(size_t)NTOK*DIM];        // 16MB fp16(x) all tokens
__device__ __half             g_Bw[(size_t)NE*DIM*DIM];      // 32MB flat fp16(w)

// ---------------- helpers (baseline PTX only: sm_80-level features) ----------
__device__ __forceinline__ uint32_t smem_u32(const void* p) {
    uint32_t a;
    asm("{ .reg .u64 t; cvta.to.shared.u64 t, %1; cvt.u32.u64 %0, t; }" : "=r"(a) : "l"(p));
    return a;
}
__device__ __forceinline__ void cp16(uint32_t d, const void* s) {
    asm volatile("cp.async.cg.shared.global [%0], [%1], 16;" :: "r"(d), "l"(s));
}
__device__ __forceinline__ void cp_commit() {
    asm volatile("cp.async.commit_group;" ::: "memory");
}
__device__ __forceinline__ void ldmx4(uint32_t* r, uint32_t addr) {
    asm volatile("ldmatrix.sync.aligned.m8n8.x4.shared.b16 {%0,%1,%2,%3}, [%4];"
                 : "=r"(r[0]), "=r"(r[1]), "=r"(r[2]), "=r"(r[3]) : "r"(addr));
}
__device__ __forceinline__ void mma_f16(float* c, const uint32_t* a, uint32_t b0, uint32_t b1) {
    asm volatile("mma.sync.aligned.m16n8k16.row.col.f32.f16.f16.f32 "
                 "{%0,%1,%2,%3}, {%4,%5,%6,%7}, {%8,%9}, {%0,%1,%2,%3};"
                 : "+f"(c[0]), "+f"(c[1]), "+f"(c[2]), "+f"(c[3])
                 : "r"(a[0]), "r"(a[1]), "r"(a[2]), "r"(a[3]), "r"(b0), "r"(b1));
}

// ---------------- kernel 1: gating + fp16 convert (two-pass, proven) ---------
__global__ void gate_kernel(const float* __restrict__ x,
                            const float* __restrict__ gw,
                            const float* __restrict__ gb) {
    // folded init: block 0 resets counters (kernel completes before build runs)
    if (blockIdx.x == 0 && threadIdx.x < NE) {
        g_cnt[threadIdx.x] = 0;
        g_keptcnt[threadIdx.x] = 0;
    }

    int warp = (blockIdx.x * blockDim.x + threadIdx.x) >> 5;
    int lane = threadIdx.x & 31;
    if (warp >= NTOK) return;
    const float* xr = x + (size_t)warp * DIM;

    float acc[NE];
#pragma unroll
    for (int e = 0; e < NE; e++) acc[e] = 0.f;

    // pass 1: gate dot (scalar coalesced reads, low register pressure)
    for (int i = 0; i < DIM / 32; i++) {
        int d = lane + 32 * i;
        float xv = xr[d];
        const float4* g4 = (const float4*)(gw + d * NE);
#pragma unroll
        for (int q = 0; q < 4; q++) {
            float4 w = g4[q];
            acc[4*q+0] += xv * w.x;
            acc[4*q+1] += xv * w.y;
            acc[4*q+2] += xv * w.z;
            acc[4*q+3] += xv * w.w;
        }
    }

    // pass 2: fp16 convert of this row (re-read from L1, contiguous 16B stores)
    {
        __half* oh = g_Ax + (size_t)warp * DIM;
#pragma unroll
        for (int i = 0; i < 4; i++) {
            int chunk = i * 32 + lane;          // 128 chunks of 8 elems
            float4 v0 = *(const float4*)(xr + chunk * 8);
            float4 v1 = *(const float4*)(xr + chunk * 8 + 4);
            unsigned short h[8] = {
                __half_as_ushort(__float2half_rn(v0.x)), __half_as_ushort(__float2half_rn(v0.y)),
                __half_as_ushort(__float2half_rn(v0.z)), __half_as_ushort(__float2half_rn(v0.w)),
                __half_as_ushort(__float2half_rn(v1.x)), __half_as_ushort(__float2half_rn(v1.y)),
                __half_as_ushort(__float2half_rn(v1.z)), __half_as_ushort(__float2half_rn(v1.w)) };
            *(uint4*)(oh + chunk * 8) =
                make_uint4((uint32_t)h[0] | ((uint32_t)h[1] << 16),
                           (uint32_t)h[2] | ((uint32_t)h[3] << 16),
                           (uint32_t)h[4] | ((uint32_t)h[5] << 16),
                           (uint32_t)h[6] | ((uint32_t)h[7] << 16));
        }
    }

#pragma unroll
    for (int e = 0; e < NE; e++) {
        float v = acc[e];
#pragma unroll
        for (int o = 16; o > 0; o >>= 1) v += __shfl_xor_sync(0xffffffffu, v, o);
        acc[e] = v;
    }

    if (lane == 0) {
        float v0 = -1e30f, v1 = -1e30f;
        int   i0 = 0, i1 = 0;
#pragma unroll
        for (int e = 0; e < NE; e++) {
            float v = acc[e] + gb[e];
            if (v > v0)      { v1 = v0; i1 = i0; v0 = v; i0 = e; }
            else if (v > v1) { v1 = v;  i1 = e; }
        }
        float t  = expf(v1 - v0);
        float s  = 1.f / (1.f + t);
        float g0 = s, g1 = t * s;        // g0 >= 0.5 always

        int s0 = 2 * warp, s1 = s0 + 1;
        g_gate[s0] = g0;  g_gate[s1] = g1;
        g_eid[s0]  = i0;  g_eid[s1]  = i1;
        unsigned long long sb = (unsigned long long)__float_as_uint(g0);
        g_key[s0] = (sb << 14) | (unsigned long long)(NS - 1 - s0);
        g_key[s1] = (sb << 14) | (unsigned long long)(NS - 1 - s1);
    }
}

// ---------------- kernel 2: slot lists, block-aggregated atomics -------------
__global__ void build_kernel() {
    __shared__ int lcnt[NE];
    __shared__ int lbase[NE];
    int t = threadIdx.x;
    int s = blockIdx.x * 256 + t;
    if (t < NE) lcnt[t] = 0;
    __syncthreads();
    int e = g_eid[s];
    int p = atomicAdd(&lcnt[e], 1);
    __syncthreads();
    if (t < NE) lbase[t] = atomicAdd(&g_cnt[t], lcnt[t]);
    __syncthreads();
    int pos = lbase[e] + p;
    g_list[e * NS + pos] = s;
    g_lkey[e * NS + pos] = g_key[s];
}

// ---------------- kernel 3: histogram-select capacity ranking ----------------
#define NBUCK 16384
#define BLCAP 8192
#define RSMEM (NBUCK*4 + BLCAP*8 + BLCAP*4)

__device__ __forceinline__ int key_bucket(unsigned long long k) {
    int diff = (int)(uint32_t)(k >> 14) - 0x3F000000;
    diff >>= 9;
    return diff < 0 ? 0 : (diff > NBUCK - 1 ? NBUCK - 1 : diff);
}

__global__ void rank_kernel() {
    extern __shared__ char rsm[];
    int* hist = (int*)rsm;
    unsigned long long* lkey = (unsigned long long*)(rsm + NBUCK * 4);
    int* lslot = (int*)(rsm + NBUCK * 4 + BLCAP * 8);

    __shared__ int ps[256];
    __shared__ int suf[256];
    __shared__ int sB, sAbove, sNB;

    int e = blockIdx.x;
    int c = g_cnt[e];
    int t = threadIdx.x;

    for (int i = t; i < NBUCK; i += 256) hist[i] = 0;
    if (t == 0) { sB = -1; sAbove = 0; sNB = 0; }
    __syncthreads();

    // pass A: histogram with 4-way batched independent loads (MLP)
    for (int i0 = t; i0 < c; i0 += 1024) {
        unsigned long long k[4]; int ok[4];
#pragma unroll
        for (int b = 0; b < 4; b++) {
            int i = i0 + 256 * b;
            ok[b] = i < c;
            k[b] = ok[b] ? g_lkey[e * NS + i] : 0ull;
        }
#pragma unroll
        for (int b = 0; b < 4; b++)
            if (ok[b]) atomicAdd(&hist[key_bucket(k[b])], 1);
    }
    __syncthreads();

    int local = 0;
#pragma unroll 8
    for (int j = 0; j < 64; j++) local += hist[t * 64 + j];
    ps[t] = local;
    __syncthreads();
    if (t == 0) {
        int run = 0;
        for (int j = 255; j >= 0; j--) { suf[j] = run; run += ps[j]; }
    }
    __syncthreads();
    if (suf[t] < CAPE && CAPE <= suf[t] + ps[t]) {
        int running = suf[t];
        for (int j = 63; j >= 0; j--) {
            int b = t * 64 + j;
            int h = hist[b];
            if (running < CAPE && CAPE <= running + h) { sB = b; sAbove = running; }
            running += h;
        }
    }
    __syncthreads();
    int B = sB, above = sAbove;

    // pass B: classify (4-way batched key/slot loads)
    for (int i0 = t; i0 < c; i0 += 1024) {
        unsigned long long k[4]; int sl[4]; int ok[4];
#pragma unroll
        for (int b = 0; b < 4; b++) {
            int i = i0 + 256 * b;
            ok[b] = i < c;
            k[b]  = ok[b] ? g_lkey[e * NS + i] : 0ull;
            sl[b] = ok[b] ? g_list[e * NS + i] : 0;
        }
#pragma unroll
        for (int b = 0; b < 4; b++) {
            if (!ok[b]) continue;
            int slot = sl[b];
            int bk = key_bucket(k[b]);
            if (bk > B || B < 0) {
                g_keep[slot] = 1;
                int p = atomicAdd(&g_keptcnt[e], 1);
                g_kept[e * CAPE + p] = slot;
            } else if (bk < B) {
                g_keep[slot] = 0;
            } else {
                int p = atomicAdd(&sNB, 1);
                if (p < BLCAP) { lkey[p] = k[b]; lslot[p] = slot; }
                else {
                    int cnt = 0;
                    for (int j = 0; j < c; j++) cnt += (g_lkey[e * NS + j] > k[b]) ? 1 : 0;
                    bool kp = cnt < CAPE;
                    g_keep[slot] = kp ? 1 : 0;
                    if (kp) { int q = atomicAdd(&g_keptcnt[e], 1); g_kept[e * CAPE + q] = slot; }
                }
            }
        }
    }
    __syncthreads();

    int nb = sNB < BLCAP ? sNB : BLCAP;
    bool overflow = sNB > BLCAP;
    for (int i = t; i < nb; i += 256) {
        unsigned long long k = lkey[i];
        int slot = lslot[i];
        int cnt = above;
        if (!overflow) {
            for (int j = 0; j < nb; j++) cnt += (lkey[j] > k) ? 1 : 0;
        } else {
            cnt = 0;
            for (int j = 0; j < c; j++) cnt += (g_lkey[e * NS + j] > k) ? 1 : 0;
        }
        bool kp = cnt < CAPE;
        g_keep[slot] = kp ? 1 : 0;
        if (kp) { int p = atomicAdd(&g_keptcnt[e], 1); g_kept[e * CAPE + p] = slot; }
    }
}

// ---------------- kernel 4: convert expert weights to fp16 (8 floats/thread) -
__global__ void convert_w_kernel(const float* __restrict__ ew) {
    size_t i8 = (size_t)blockIdx.x * blockDim.x + threadIdx.x;
    size_t g  = i8 * 8;
    float4 v0 = *(const float4*)(ew + g);
    float4 v1 = *(const float4*)(ew + g + 4);
    unsigned short h[8] = {
        __half_as_ushort(__float2half_rn(v0.x)), __half_as_ushort(__float2half_rn(v0.y)),
        __half_as_ushort(__float2half_rn(v0.z)), __half_as_ushort(__float2half_rn(v0.w)),
        __half_as_ushort(__float2half_rn(v1.x)), __half_as_ushort(__float2half_rn(v1.y)),
        __half_as_ushort(__float2half_rn(v1.z)), __half_as_ushort(__float2half_rn(v1.w)) };
    *(uint4*)(g_Bw + g) =
        make_uint4((uint32_t)h[0] | ((uint32_t)h[1] << 16),
                   (uint32_t)h[2] | ((uint32_t)h[3] << 16),
                   (uint32_t)h[4] | ((uint32_t)h[5] << 16),
                   (uint32_t)h[6] | ((uint32_t)h[7] << 16));
}

// ---------------- kernel 5: warp-MMA (HMMA) expert GEMM, K=1024 --------------
// PROVEN CONFIG: BM=128, BN=128, BK=32, 4-stage cp.async,
// single sync per k-chunk, prefetch right after barrier.
#define GBM 128
#define GBN 128
#define NKC 32
#define NSTAGE 4
#define STAGE_BYTES 16384                       // A 8KB + B 8KB
#define GEMM_SMEM (NSTAGE*STAGE_BYTES + GBM*8)

struct GCtx {
    const __half* Bb;
    const int* stok;       // smem token table
    uint32_t sb;
    int t;
};

__device__ __forceinline__ void g_load(const GCtx& c, int kc) {
    int k0 = kc * 32;
    uint32_t st = c.sb + (kc % NSTAGE) * STAGE_BYTES;
#pragma unroll
    for (int j = 0; j < 2; j++) {               // A: 128 rows x 4 chunks(16B)
        int s = c.t + 256 * j;
        int row = s >> 2, ch = s & 3;
        uint32_t dst = st + row * 64 + ((ch ^ ((row >> 1) & 3)) << 4);
        cp16(dst, g_Ax + (size_t)c.stok[row] * DIM + k0 + ch * 8);
    }
#pragma unroll
    for (int j = 0; j < 2; j++) {               // B: 128 rows x 4 chunks(16B)
        int s = c.t + 256 * j;
        int row = s >> 2, ch = s & 3;
        uint32_t dst = st + 8192 + row * 64 + ((ch ^ ((row >> 1) & 3)) << 4);
        cp16(dst, c.Bb + (size_t)row * DIM + k0 + ch * 8);
    }
    cp_commit();
}

__global__ void __launch_bounds__(256, 2)
moe_gemm_mma(const float* __restrict__ eb) {
    extern __shared__ char smem[];
    int e    = blockIdx.z;
    int mcnt = g_keptcnt[e];
    int m0   = blockIdx.y * GBM;
    if (m0 >= mcnt) return;
    int n0   = blockIdx.x * GBN;

    uint32_t sb = smem_u32(smem);
    int t = threadIdx.x;
    int w = t >> 5, l = t & 31;
    int wm = w & 3, wn = w >> 2;

    int* sslot = (int*)(smem + NSTAGE * STAGE_BYTES);
    int* stok  = sslot + GBM;
    if (t < GBM) {
        int mi = m0 + t;
        int slot = (mi < mcnt) ? g_kept[e * CAPE + mi] : -1;
        sslot[t] = slot;
        stok[t]  = (slot >= 0) ? (slot >> 1) : 0;
    }
    __syncthreads();

    GCtx c;
    c.Bb   = g_Bw + (size_t)(e * DIM + n0) * DIM;
    c.stok = stok;
    c.sb   = sb;
    c.t    = t;

    g_load(c, 0);
    g_load(c, 1);
    g_load(c, 2);

    float acc[2][8][4];
#pragma unroll
    for (int i = 0; i < 2; i++)
#pragma unroll
        for (int j = 0; j < 8; j++)
#pragma unroll
            for (int q = 0; q < 4; q++) acc[i][j][q] = 0.f;

    int sub = l >> 3, lr = l & 7;
    int a_row = wm * 32 + lr + ((sub & 1) << 3);   // + mt*16
    int a_cs  = sub >> 1;
    int b_row = wn * 64 + lr + ((sub >> 1) << 3);  // + j*16
    int b_cs  = sub & 1;

    for (int kc = 0; kc < NKC; kc++) {
        asm volatile("cp.async.wait_group 2;" ::: "memory");
        __syncthreads();
        // prefetch stage kc+3 (writes stage (kc-1)%4; all warps finished its
        // compute before this iteration's barrier)
        if (kc + 3 < NKC) g_load(c, kc + 3);
        else cp_commit();

        uint32_t sA = sb + (kc % NSTAGE) * STAGE_BYTES;
        uint32_t sB = sA + 8192;
#pragma unroll
        for (int ks = 0; ks < 2; ks++) {
            uint32_t areg[2][4];
#pragma unroll
            for (int mt = 0; mt < 2; mt++) {
                int row = a_row + mt * 16;
                int kch = ks * 2 + a_cs;
                ldmx4(areg[mt], sA + row * 64 + ((kch ^ ((row >> 1) & 3)) << 4));
            }
#pragma unroll
            for (int j = 0; j < 4; j++) {
                int row = b_row + j * 16;
                int kch = ks * 2 + b_cs;
                uint32_t breg[4];
                ldmx4(breg, sB + row * 64 + ((kch ^ ((row >> 1) & 3)) << 4));
#pragma unroll
                for (int mt = 0; mt < 2; mt++) {
                    mma_f16(acc[mt][2*j],   areg[mt], breg[0], breg[1]);
                    mma_f16(acc[mt][2*j+1], areg[mt], breg[2], breg[3]);
                }
            }
        }
    }

    // epilogue: bias + scatter fp16 to per-slot Y
    const float* br = eb + (size_t)e * DIM + n0;
#pragma unroll
    for (int mt = 0; mt < 2; mt++) {
        int r0 = wm * 32 + mt * 16 + (l >> 2);
        int s0 = sslot[r0], s1 = sslot[r0 + 8];
#pragma unroll
        for (int nt = 0; nt < 8; nt++) {
            int col = wn * 64 + nt * 8 + (l & 3) * 2;
            float2 bv = *(const float2*)(br + col);
            if (s0 >= 0) {
                __half2 h = __floats2half2_rn(acc[mt][nt][0] + bv.x, acc[mt][nt][1] + bv.y);
                *(__half2*)(g_Yh + (size_t)s0 * DIM + n0 + col) = h;
            }
            if (s1 >= 0) {
                __half2 h = __floats2half2_rn(acc[mt][nt][2] + bv.x, acc[mt][nt][3] + bv.y);
                *(__half2*)(g_Yh + (size_t)s1 * DIM + n0 + col) = h;
            }
        }
    }
}

// ---------------- kernel 6: combine ------------------------------------------
__global__ void combine_kernel(const float* __restrict__ x, float* __restrict__ out) {
    int idx = blockIdx.x * blockDim.x + threadIdx.x;
    if (idx >= NTOK * DIM / 4) return;
    int n  = idx >> 8;
    int dq = idx & 255;

    float g0 = g_gate[2 * n], g1 = g_gate[2 * n + 1];
    bool  k0 = g_keep[2 * n] != 0, k1 = g_keep[2 * n + 1] != 0;

    float4 xv = ((const float4*)x)[(size_t)n * 256 + dq];

    float y0[4], y1[4];
    if (k0) {
        const __half2* p = (const __half2*)(g_Yh + (size_t)(2 * n) * DIM + dq * 4);
        float2 a = __half22float2(p[0]), b = __half22float2(p[1]);
        y0[0] = a.x; y0[1] = a.y; y0[2] = b.x; y0[3] = b.y;
    } else { y0[0] = xv.x; y0[1] = xv.y; y0[2] = xv.z; y0[3] = xv.w; }
    if (k1) {
        const __half2* p = (const __half2*)(g_Yh + (size_t)(2 * n + 1) * DIM + dq * 4);
        float2 a = __half22float2(p[0]), b = __half22float2(p[1]);
        y1[0] = a.x; y1[1] = a.y; y1[2] = b.x; y1[3] = b.y;
    } else { y1[0] = xv.x; y1[1] = xv.y; y1[2] = xv.z; y1[3] = xv.w; }

    float4 o;
    o.x = g0 * y0[0] + g1 * y1[0];
    o.y = g0 * y0[1] + g1 * y1[1];
    o.z = g0 * y0[2] + g1 * y1[2];
    o.w = g0 * y0[3] + g1 * y1[3];
    ((float4*)out)[idx] = o;
}

// ---------------- launch ------------------------------------------------------
extern "C" void kernel_launch(void* const* d_in, const int* in_sizes, int n_in,
                              void* d_out, int out_size) {
    const float* moe_inp  = (const float*)d_in[0];
    const float* gate_w   = (const float*)d_in[1];
    const float* gate_b   = (const float*)d_in[2];
    const float* expert_w = (const float*)d_in[3];
    const float* expert_b = (const float*)d_in[4];
    float* out = (float*)d_out;

    (void)in_sizes; (void)n_in; (void)out_size;

    cudaFuncSetAttribute(rank_kernel, cudaFuncAttributeMaxDynamicSharedMemorySize, RSMEM);
    cudaFuncSetAttribute(moe_gemm_mma, cudaFuncAttributeMaxDynamicSharedMemorySize,
                         GEMM_SMEM);

    gate_kernel<<<NTOK / 8, 256>>>(moe_inp, gate_w, gate_b);
    convert_w_kernel<<<(NE * DIM * DIM / 8) / 256, 256>>>(expert_w);
    build_kernel<<<NS / 256, 256>>>();
    rank_kernel<<<NE, 256, RSMEM>>>();
    moe_gemm_mma<<<dim3(DIM / GBN, CAPE / GBM, NE), 256, GEMM_SMEM>>>(expert_b);
    combine_kernel<<<(NTOK * DIM / 4 + 255) / 256, 256>>>(moe_inp, out);
}

// round 17
// speedup vs baseline: 1.3020x; 1.0672x over previous
#include <cuda_runtime.h>
#include <cuda_fp16.h>
#include <math.h>
#include <stdint.h>

// Problem constants
#define NTOK 8192
#define DIM  1024
#define NE   16
#define CAPE 1024
#define NS   (NTOK*2)

// ---------------- scratch (static device globals) ----------------------------
__device__ float              g_gate[NS];
__device__ unsigned long long g_key[NS];
__device__ int                g_eid[NS];
__device__ int                g_cnt[NE];
__device__ int                g_list[NE*NS];
__device__ unsigned long long g_lkey[NE*NS];
__device__ int                g_keptcnt[NE];
__device__ int                g_kept[NE*CAPE];
__device__ unsigned char      g_keep[NS];
__device__ __half             g_Yh[(size_t)NS*DIM];          // 32MB fp16 expert outputs
__device__ __half             g_Ax[(size_t)NTOK*DIM];        // 16MB fp16(x) all tokens
__device__ __half             g_Bw[(size_t)NE*DIM*DIM];      // 32MB flat fp16(w)

// ---------------- helpers (baseline PTX only: sm_80-level features) ----------
__device__ __forceinline__ uint32_t smem_u32(const void* p) {
    uint32_t a;
    asm("{ .reg .u64 t; cvta.to.shared.u64 t, %1; cvt.u32.u64 %0, t; }" : "=r"(a) : "l"(p));
    return a;
}
__device__ __forceinline__ void cp16(uint32_t d, const void* s) {
    asm volatile("cp.async.cg.shared.global [%0], [%1], 16;" :: "r"(d), "l"(s));
}
__device__ __forceinline__ void cp_commit() {
    asm volatile("cp.async.commit_group;" ::: "memory");
}
__device__ __forceinline__ void ldmx4(uint32_t* r, uint32_t addr) {
    asm volatile("ldmatrix.sync.aligned.m8n8.x4.shared.b16 {%0,%1,%2,%3}, [%4];"
                 : "=r"(r[0]), "=r"(r[1]), "=r"(r[2]), "=r"(r[3]) : "r"(addr));
}
__device__ __forceinline__ void mma_f16(float* c, const uint32_t* a, uint32_t b0, uint32_t b1) {
    asm volatile("mma.sync.aligned.m16n8k16.row.col.f32.f16.f16.f32 "
                 "{%0,%1,%2,%3}, {%4,%5,%6,%7}, {%8,%9}, {%0,%1,%2,%3};"
                 : "+f"(c[0]), "+f"(c[1]), "+f"(c[2]), "+f"(c[3])
                 : "r"(a[0]), "r"(a[1]), "r"(a[2]), "r"(a[3]), "r"(b0), "r"(b1));
}

// ---------------- kernel 1: gating + fp16 convert (two-pass, proven) ---------
__global__ void gate_kernel(const float* __restrict__ x,
                            const float* __restrict__ gw,
                            const float* __restrict__ gb) {
    // folded init: block 0 resets counters (kernel completes before build runs)
    if (blockIdx.x == 0 && threadIdx.x < NE) {
        g_cnt[threadIdx.x] = 0;
        g_keptcnt[threadIdx.x] = 0;
    }

    int warp = (blockIdx.x * blockDim.x + threadIdx.x) >> 5;
    int lane = threadIdx.x & 31;
    if (warp >= NTOK) return;
    const float* xr = x + (size_t)warp * DIM;

    float acc[NE];
#pragma unroll
    for (int e = 0; e < NE; e++) acc[e] = 0.f;

    // pass 1: gate dot (scalar coalesced reads, low register pressure)
    for (int i = 0; i < DIM / 32; i++) {
        int d = lane + 32 * i;
        float xv = xr[d];
        const float4* g4 = (const float4*)(gw + d * NE);
#pragma unroll
        for (int q = 0; q < 4; q++) {
            float4 w = g4[q];
            acc[4*q+0] += xv * w.x;
            acc[4*q+1] += xv * w.y;
            acc[4*q+2] += xv * w.z;
            acc[4*q+3] += xv * w.w;
        }
    }

    // pass 2: fp16 convert of this row (re-read from L1, contiguous 16B stores)
    {
        __half* oh = g_Ax + (size_t)warp * DIM;
#pragma unroll
        for (int i = 0; i < 4; i++) {
            int chunk = i * 32 + lane;          // 128 chunks of 8 elems
            float4 v0 = *(const float4*)(xr + chunk * 8);
            float4 v1 = *(const float4*)(xr + chunk * 8 + 4);
            unsigned short h[8] = {
                __half_as_ushort(__float2half_rn(v0.x)), __half_as_ushort(__float2half_rn(v0.y)),
                __half_as_ushort(__float2half_rn(v0.z)), __half_as_ushort(__float2half_rn(v0.w)),
                __half_as_ushort(__float2half_rn(v1.x)), __half_as_ushort(__float2half_rn(v1.y)),
                __half_as_ushort(__float2half_rn(v1.z)), __half_as_ushort(__float2half_rn(v1.w)) };
            *(uint4*)(oh + chunk * 8) =
                make_uint4((uint32_t)h[0] | ((uint32_t)h[1] << 16),
                           (uint32_t)h[2] | ((uint32_t)h[3] << 16),
                           (uint32_t)h[4] | ((uint32_t)h[5] << 16),
                           (uint32_t)h[6] | ((uint32_t)h[7] << 16));
        }
    }

#pragma unroll
    for (int e = 0; e < NE; e++) {
        float v = acc[e];
#pragma unroll
        for (int o = 16; o > 0; o >>= 1) v += __shfl_xor_sync(0xffffffffu, v, o);
        acc[e] = v;
    }

    if (lane == 0) {
        float v0 = -1e30f, v1 = -1e30f;
        int   i0 = 0, i1 = 0;
#pragma unroll
        for (int e = 0; e < NE; e++) {
            float v = acc[e] + gb[e];
            if (v > v0)      { v1 = v0; i1 = i0; v0 = v; i0 = e; }
            else if (v > v1) { v1 = v;  i1 = e; }
        }
        float t  = expf(v1 - v0);
        float s  = 1.f / (1.f + t);
        float g0 = s, g1 = t * s;        // g0 >= 0.5 always

        int s0 = 2 * warp, s1 = s0 + 1;
        g_gate[s0] = g0;  g_gate[s1] = g1;
        g_eid[s0]  = i0;  g_eid[s1]  = i1;
        unsigned long long sb = (unsigned long long)__float_as_uint(g0);
        g_key[s0] = (sb << 14) | (unsigned long long)(NS - 1 - s0);
        g_key[s1] = (sb << 14) | (unsigned long long)(NS - 1 - s1);
    }
}

// ---------------- kernel 2: slot lists, block-aggregated atomics -------------
__global__ void build_kernel() {
    __shared__ int lcnt[NE];
    __shared__ int lbase[NE];
    int t = threadIdx.x;
    int s = blockIdx.x * 256 + t;
    if (t < NE) lcnt[t] = 0;
    __syncthreads();
    int e = g_eid[s];
    int p = atomicAdd(&lcnt[e], 1);
    __syncthreads();
    if (t < NE) lbase[t] = atomicAdd(&g_cnt[t], lcnt[t]);
    __syncthreads();
    int pos = lbase[e] + p;
    g_list[e * NS + pos] = s;
    g_lkey[e * NS + pos] = g_key[s];
}

// ---------------- kernel 3: histogram-select capacity ranking ----------------
// 512 threads, parallel suffix scan (no serial thread-0 loop).
#define NBUCK 16384
#define BLCAP 8192
#define RSMEM (NBUCK*4 + BLCAP*8 + BLCAP*4)
#define RTHREADS 512
#define SEGB (NBUCK/RTHREADS)          // 32 buckets per segment

__device__ __forceinline__ int key_bucket(unsigned long long k) {
    int diff = (int)(uint32_t)(k >> 14) - 0x3F000000;
    diff >>= 9;
    return diff < 0 ? 0 : (diff > NBUCK - 1 ? NBUCK - 1 : diff);
}

__global__ void rank_kernel() {
    extern __shared__ char rsm[];
    int* hist = (int*)rsm;
    unsigned long long* lkey = (unsigned long long*)(rsm + NBUCK * 4);
    int* lslot = (int*)(rsm + NBUCK * 4 + BLCAP * 8);

    __shared__ int ps[RTHREADS];       // per-segment sums -> inclusive suffix
    __shared__ int sB, sAbove, sNB;

    int e = blockIdx.x;
    int c = g_cnt[e];
    int t = threadIdx.x;

    for (int i = t; i < NBUCK; i += RTHREADS) hist[i] = 0;
    if (t == 0) { sB = -1; sAbove = 0; sNB = 0; }
    __syncthreads();

    // pass A: histogram (batched independent loads)
    for (int i0 = t; i0 < c; i0 += RTHREADS * 4) {
        unsigned long long k[4]; int ok[4];
#pragma unroll
        for (int b = 0; b < 4; b++) {
            int i = i0 + RTHREADS * b;
            ok[b] = i < c;
            k[b] = ok[b] ? g_lkey[e * NS + i] : 0ull;
        }
#pragma unroll
        for (int b = 0; b < 4; b++)
            if (ok[b]) atomicAdd(&hist[key_bucket(k[b])], 1);
    }
    __syncthreads();

    // segment sums (32 buckets/thread)
    int local = 0;
#pragma unroll
    for (int j = 0; j < SEGB; j++) local += hist[t * SEGB + j];
    ps[t] = local;
    __syncthreads();

    // parallel inclusive suffix scan over ps[512] (Hillis-Steele, 9 steps)
#pragma unroll
    for (int off = 1; off < RTHREADS; off <<= 1) {
        int v = ps[t];
        int add = (t + off < RTHREADS) ? ps[t + off] : 0;
        __syncthreads();
        ps[t] = v + add;
        __syncthreads();
    }
    // ps[t] = sum of segments [t, 512); exclusive suffix of segment t:
    int mySuf = (t + 1 < RTHREADS) ? ps[t + 1] : 0;

    // the unique segment straddling CAPE walks its buckets
    if (mySuf < CAPE && CAPE <= mySuf + local) {
        int running = mySuf;
        for (int j = SEGB - 1; j >= 0; j--) {
            int b = t * SEGB + j;
            int h = hist[b];
            if (running < CAPE && CAPE <= running + h) { sB = b; sAbove = running; }
            running += h;
        }
    }
    __syncthreads();
    int B = sB, above = sAbove;

    // pass B: classify (batched loads)
    for (int i0 = t; i0 < c; i0 += RTHREADS * 4) {
        unsigned long long k[4]; int sl[4]; int ok[4];
#pragma unroll
        for (int b = 0; b < 4; b++) {
            int i = i0 + RTHREADS * b;
            ok[b] = i < c;
            k[b]  = ok[b] ? g_lkey[e * NS + i] : 0ull;
            sl[b] = ok[b] ? g_list[e * NS + i] : 0;
        }
#pragma unroll
        for (int b = 0; b < 4; b++) {
            if (!ok[b]) continue;
            int slot = sl[b];
            int bk = key_bucket(k[b]);
            if (bk > B || B < 0) {
                g_keep[slot] = 1;
                int p = atomicAdd(&g_keptcnt[e], 1);
                g_kept[e * CAPE + p] = slot;
            } else if (bk < B) {
                g_keep[slot] = 0;
            } else {
                int p = atomicAdd(&sNB, 1);
                if (p < BLCAP) { lkey[p] = k[b]; lslot[p] = slot; }
                else {
                    int cnt = 0;
                    for (int j = 0; j < c; j++) cnt += (g_lkey[e * NS + j] > k[b]) ? 1 : 0;
                    bool kp = cnt < CAPE;
                    g_keep[slot] = kp ? 1 : 0;
                    if (kp) { int q = atomicAdd(&g_keptcnt[e], 1); g_kept[e * CAPE + q] = slot; }
                }
            }
        }
    }
    __syncthreads();

    int nb = sNB < BLCAP ? sNB : BLCAP;
    bool overflow = sNB > BLCAP;
    for (int i = t; i < nb; i += RTHREADS) {
        unsigned long long k = lkey[i];
        int slot = lslot[i];
        int cnt = above;
        if (!overflow) {
            for (int j = 0; j < nb; j++) cnt += (lkey[j] > k) ? 1 : 0;
        } else {
            cnt = 0;
            for (int j = 0; j < c; j++) cnt += (g_lkey[e * NS + j] > k) ? 1 : 0;
        }
        bool kp = cnt < CAPE;
        g_keep[slot] = kp ? 1 : 0;
        if (kp) { int p = atomicAdd(&g_keptcnt[e], 1); g_kept[e * CAPE + p] = slot; }
    }
}

// ---------------- kernel 4: convert expert weights to fp16 (8 floats/thread) -
__global__ void convert_w_kernel(const float* __restrict__ ew) {
    size_t i8 = (size_t)blockIdx.x * blockDim.x + threadIdx.x;
    size_t g  = i8 * 8;
    float4 v0 = *(const float4*)(ew + g);
    float4 v1 = *(const float4*)(ew + g + 4);
    unsigned short h[8] = {
        __half_as_ushort(__float2half_rn(v0.x)), __half_as_ushort(__float2half_rn(v0.y)),
        __half_as_ushort(__float2half_rn(v0.z)), __half_as_ushort(__float2half_rn(v0.w)),
        __half_as_ushort(__float2half_rn(v1.x)), __half_as_ushort(__float2half_rn(v1.y)),
        __half_as_ushort(__float2half_rn(v1.z)), __half_as_ushort(__float2half_rn(v1.w)) };
    *(uint4*)(g_Bw + g) =
        make_uint4((uint32_t)h[0] | ((uint32_t)h[1] << 16),
                   (uint32_t)h[2] | ((uint32_t)h[3] << 16),
                   (uint32_t)h[4] | ((uint32_t)h[5] << 16),
                   (uint32_t)h[6] | ((uint32_t)h[7] << 16));
}

// ---------------- kernel 5: warp-MMA (HMMA) expert GEMM, K=1024 --------------
// PROVEN CONFIG: BM=128, BN=128, BK=32, 4-stage cp.async,
// single sync per k-chunk, prefetch right after barrier.
#define GBM 128
#define GBN 128
#define NKC 32
#define NSTAGE 4
#define STAGE_BYTES 16384                       // A 8KB + B 8KB
#define GEMM_SMEM (NSTAGE*STAGE_BYTES + GBM*8)

struct GCtx {
    const __half* Bb;
    const int* stok;       // smem token table
    uint32_t sb;
    int t;
};

__device__ __forceinline__ void g_load(const GCtx& c, int kc) {
    int k0 = kc * 32;
    uint32_t st = c.sb + (kc % NSTAGE) * STAGE_BYTES;
#pragma unroll
    for (int j = 0; j < 2; j++) {               // A: 128 rows x 4 chunks(16B)
        int s = c.t + 256 * j;
        int row = s >> 2, ch = s & 3;
        uint32_t dst = st + row * 64 + ((ch ^ ((row >> 1) & 3)) << 4);
        cp16(dst, g_Ax + (size_t)c.stok[row] * DIM + k0 + ch * 8);
    }
#pragma unroll
    for (int j = 0; j < 2; j++) {               // B: 128 rows x 4 chunks(16B)
        int s = c.t + 256 * j;
        int row = s >> 2, ch = s & 3;
        uint32_t dst = st + 8192 + row * 64 + ((ch ^ ((row >> 1) & 3)) << 4);
        cp16(dst, c.Bb + (size_t)row * DIM + k0 + ch * 8);
    }
    cp_commit();
}

__global__ void __launch_bounds__(256, 2)
moe_gemm_mma(const float* __restrict__ eb) {
    extern __shared__ char smem[];
    int e    = blockIdx.z;
    int mcnt = g_keptcnt[e];
    int m0   = blockIdx.y * GBM;
    if (m0 >= mcnt) return;
    int n0   = blockIdx.x * GBN;

    uint32_t sb = smem_u32(smem);
    int t = threadIdx.x;
    int w = t >> 5, l = t & 31;
    int wm = w & 3, wn = w >> 2;

    int* sslot = (int*)(smem + NSTAGE * STAGE_BYTES);
    int* stok  = sslot + GBM;
    if (t < GBM) {
        int mi = m0 + t;
        int slot = (mi < mcnt) ? g_kept[e * CAPE + mi] : -1;
        sslot[t] = slot;
        stok[t]  = (slot >= 0) ? (slot >> 1) : 0;
    }
    __syncthreads();

    GCtx c;
    c.Bb   = g_Bw + (size_t)(e * DIM + n0) * DIM;
    c.stok = stok;
    c.sb   = sb;
    c.t    = t;

    g_load(c, 0);
    g_load(c, 1);
    g_load(c, 2);

    float acc[2][8][4];
#pragma unroll
    for (int i = 0; i < 2; i++)
#pragma unroll
        for (int j = 0; j < 8; j++)
#pragma unroll
            for (int q = 0; q < 4; q++) acc[i][j][q] = 0.f;

    int sub = l >> 3, lr = l & 7;
    int a_row = wm * 32 + lr + ((sub & 1) << 3);   // + mt*16
    int a_cs  = sub >> 1;
    int b_row = wn * 64 + lr + ((sub >> 1) << 3);  // + j*16
    int b_cs  = sub & 1;

    for (int kc = 0; kc < NKC; kc++) {
        asm volatile("cp.async.wait_group 2;" ::: "memory");
        __syncthreads();
        // prefetch stage kc+3 (writes stage (kc-1)%4; all warps finished its
        // compute before this iteration's barrier)
        if (kc + 3 < NKC) g_load(c, kc + 3);
        else cp_commit();

        uint32_t sA = sb + (kc % NSTAGE) * STAGE_BYTES;
        uint32_t sB = sA + 8192;
#pragma unroll
        for (int ks = 0; ks < 2; ks++) {
            uint32_t areg[2][4];
#pragma unroll
            for (int mt = 0; mt < 2; mt++) {
                int row = a_row + mt * 16;
                int kch = ks * 2 + a_cs;
                ldmx4(areg[mt], sA + row * 64 + ((kch ^ ((row >> 1) & 3)) << 4));
            }
#pragma unroll
            for (int j = 0; j < 4; j++) {
                int row = b_row + j * 16;
                int kch = ks * 2 + b_cs;
                uint32_t breg[4];
                ldmx4(breg, sB + row * 64 + ((kch ^ ((row >> 1) & 3)) << 4));
#pragma unroll
                for (int mt = 0; mt < 2; mt++) {
                    mma_f16(acc[mt][2*j],   areg[mt], breg[0], breg[1]);
                    mma_f16(acc[mt][2*j+1], areg[mt], breg[2], breg[3]);
                }
            }
        }
    }

    // epilogue: bias + scatter fp16 to per-slot Y
    const float* br = eb + (size_t)e * DIM + n0;
#pragma unroll
    for (int mt = 0; mt < 2; mt++) {
        int r0 = wm * 32 + mt * 16 + (l >> 2);
        int s0 = sslot[r0], s1 = sslot[r0 + 8];
#pragma unroll
        for (int nt = 0; nt < 8; nt++) {
            int col = wn * 64 + nt * 8 + (l & 3) * 2;
            float2 bv = *(const float2*)(br + col);
            if (s0 >= 0) {
                __half2 h = __floats2half2_rn(acc[mt][nt][0] + bv.x, acc[mt][nt][1] + bv.y);
                *(__half2*)(g_Yh + (size_t)s0 * DIM + n0 + col) = h;
            }
            if (s1 >= 0) {
                __half2 h = __floats2half2_rn(acc[mt][nt][2] + bv.x, acc[mt][nt][3] + bv.y);
                *(__half2*)(g_Yh + (size_t)s1 * DIM + n0 + col) = h;
            }
        }
    }
}

// ---------------- kernel 6: combine (x load only when a slot dropped) --------
__global__ void combine_kernel(const float* __restrict__ x, float* __restrict__ out) {
    int idx = blockIdx.x * blockDim.x + threadIdx.x;
    if (idx >= NTOK * DIM / 4) return;
    int n  = idx >> 8;
    int dq = idx & 255;

    float g0 = g_gate[2 * n], g1 = g_gate[2 * n + 1];
    bool  k0 = g_keep[2 * n] != 0, k1 = g_keep[2 * n + 1] != 0;

    float4 xv = make_float4(0.f, 0.f, 0.f, 0.f);
    if (!(k0 && k1))                    // warp-uniform: all lanes share n
        xv = ((const float4*)x)[(size_t)n * 256 + dq];

    float y0[4], y1[4];
    if (k0) {
        const __half2* p = (const __half2*)(g_Yh + (size_t)(2 * n) * DIM + dq * 4);
        float2 a = __half22float2(p[0]), b = __half22float2(p[1]);
        y0[0] = a.x; y0[1] = a.y; y0[2] = b.x; y0[3] = b.y;
    } else { y0[0] = xv.x; y0[1] = xv.y; y0[2] = xv.z; y0[3] = xv.w; }
    if (k1) {
        const __half2* p = (const __half2*)(g_Yh + (size_t)(2 * n + 1) * DIM + dq * 4);
        float2 a = __half22float2(p[0]), b = __half22float2(p[1]);
        y1[0] = a.x; y1[1] = a.y; y1[2] = b.x; y1[3] = b.y;
    } else { y1[0] = xv.x; y1[1] = xv.y; y1[2] = xv.z; y1[3] = xv.w; }

    float4 o;
    o.x = g0 * y0[0] + g1 * y1[0];
    o.y = g0 * y0[1] + g1 * y1[1];
    o.z = g0 * y0[2] + g1 * y1[2];
    o.w = g0 * y0[3] + g1 * y1[3];
    ((float4*)out)[idx] = o;
}

// ---------------- launch ------------------------------------------------------
extern "C" void kernel_launch(void* const* d_in, const int* in_sizes, int n_in,
                              void* d_out, int out_size) {
    const float* moe_inp  = (const float*)d_in[0];
    const float* gate_w   = (const float*)d_in[1];
    const float* gate_b   = (const float*)d_in[2];
    const float* expert_w = (const float*)d_in[3];
    const float* expert_b = (const float*)d_in[4];
    float* out = (float*)d_out;

    (void)in_sizes; (void)n_in; (void)out_size;

    cudaFuncSetAttribute(rank_kernel, cudaFuncAttributeMaxDynamicSharedMemorySize, RSMEM);
    cudaFuncSetAttribute(moe_gemm_mma, cudaFuncAttributeMaxDynamicSharedMemorySize,
                         GEMM_SMEM);

    gate_kernel<<<NTOK / 8, 256>>>(moe_inp, gate_w, gate_b);
    convert_w_kernel<<<(NE * DIM * DIM / 8) / 256, 256>>>(expert_w);
    build_kernel<<<NS / 256, 256>>>();
    rank_kernel<<<NE, RTHREADS, RSMEM>>>();
    moe_gemm_mma<<<dim3(DIM / GBN, CAPE / GBM, NE), 256, GEMM_SMEM>>>(expert_b);
    combine_kernel<<<(NTOK * DIM / 4 + 255) / 256, 256>>>(moe_inp, out);
}